// round 5
// baseline (speedup 1.0000x reference)
#include <cuda_runtime.h>

// Divergence of (average(M) * gradient(mu)) with periodic boundaries.
// Shapes: (B=16, C=1, H=1024, W=1024) fp32.
// out[p] = sum_ax [ v_ax(p) - v_ax(p - e_ax) ],  v_ax(p) = 0.5*(M[p+e]+M[p])*(mu[p+e]-mu[p])
//
// Rolling-window kernel: each thread owns one float4 column and walks an
// 8-row strip. A 3-row register window (prev/cur/next) provides the vertical
// stencil; each iteration prefetches row h+2 (2 independent float4 loads),
// computes row h from registers, and stores. Horizontal halos via warp
// shuffle; lanes 0/31 load one wrap-aware scalar per row per array.

#define H_DIM 1024
#define W_DIM 1024
#define N_IMG 16
#define STRIP 8

__device__ __forceinline__ float4 ldv(const float* __restrict__ p, int h, int wb)
{
    return *reinterpret_cast<const float4*>(p + ((size_t)h << 10) + wb);
}

__device__ __forceinline__ float4 row_result(
    const float4 m, const float4 u,
    float mL, float uL, float mR, float uR,
    const float4 mup, const float4 uup,
    const float4 mdn, const float4 udn)
{
    // W-direction forward fluxes (backward flux of elem e == forward of e-1)
    float vm = 0.5f * (m.x + mL)  * (u.x - uL);
    float v0 = 0.5f * (m.y + m.x) * (u.y - u.x);
    float v1 = 0.5f * (m.z + m.y) * (u.z - u.y);
    float v2 = 0.5f * (m.w + m.z) * (u.w - u.z);
    float v3 = 0.5f * (mR  + m.w) * (uR  - u.w);

    float4 r;
    r.x = (v0 - vm) + 0.5f * (mdn.x + m.x) * (udn.x - u.x) - 0.5f * (m.x + mup.x) * (u.x - uup.x);
    r.y = (v1 - v0) + 0.5f * (mdn.y + m.y) * (udn.y - u.y) - 0.5f * (m.y + mup.y) * (u.y - uup.y);
    r.z = (v2 - v1) + 0.5f * (mdn.z + m.z) * (udn.z - u.z) - 0.5f * (m.z + mup.z) * (u.z - uup.z);
    r.w = (v3 - v2) + 0.5f * (mdn.w + m.w) * (udn.w - u.w) - 0.5f * (m.w + mup.w) * (u.w - uup.w);
    return r;
}

__global__ __launch_bounds__(256) void div_grad_kernel(
    const float* __restrict__ M,
    const float* __restrict__ mu,
    float* __restrict__ out)
{
    const int lane  = threadIdx.x & 31;
    const int strip = blockIdx.x & 127;    // 128 strips of 8 rows
    const int img   = blockIdx.x >> 7;

    const int h0 = strip << 3;
    const size_t base = (size_t)img << 20;
    const float* Mi = M  + base;
    const float* Ui = mu + base;
    float* Oi = out + base;

    const int wb = threadIdx.x << 2;
    const int wl = (wb - 1) & (W_DIM - 1);
    const int wr = (wb + 4) & (W_DIM - 1);

    // Prologue: rows h0-1, h0, h0+1 (6 independent loads)
    const int hm = (h0 - 1) & (H_DIM - 1);
    float4 mp = ldv(Mi, hm, wb);
    float4 up = ldv(Ui, hm, wb);
    float4 mc = ldv(Mi, h0, wb);
    float4 uc = ldv(Ui, h0, wb);
    float4 mn = ldv(Mi, h0 + 1, wb);
    float4 un = ldv(Ui, h0 + 1, wb);

    const unsigned FULL = 0xffffffffu;

    #pragma unroll
    for (int r = 0; r < STRIP; ++r) {
        const int h = h0 + r;

        // Depth-1 prefetch: row h+2 (feeds iteration r+1's "next")
        float4 mt, ut;
        if (r < STRIP - 1) {
            const int hn = (h + 2) & (H_DIM - 1);
            mt = ldv(Mi, hn, wb);
            ut = ldv(Ui, hn, wb);
        }

        // Boundary-lane halo scalars for the current row (L1/L2 hits)
        const float* Mrow = Mi + ((size_t)h << 10);
        const float* Urow = Ui + ((size_t)h << 10);
        float bM = 0.f, bU = 0.f;
        if (lane == 0)       { bM = Mrow[wl]; bU = Urow[wl]; }
        else if (lane == 31) { bM = Mrow[wr]; bU = Urow[wr]; }

        float lM = __shfl_up_sync(FULL, mc.w, 1);
        float lU = __shfl_up_sync(FULL, uc.w, 1);
        float rM = __shfl_down_sync(FULL, mc.x, 1);
        float rU = __shfl_down_sync(FULL, uc.x, 1);
        if (lane == 0)       { lM = bM; lU = bU; }
        else if (lane == 31) { rM = bM; rU = bU; }

        float4 res = row_result(mc, uc, lM, lU, rM, rU, mp, up, mn, un);

        // Streaming store: output is never re-read, keep it out of L2's way
        __stcs(reinterpret_cast<float4*>(Oi + ((size_t)h << 10) + wb), res);

        // Rotate window
        mp = mc; up = uc;
        mc = mn; uc = un;
        mn = mt; un = ut;
    }
}

extern "C" void kernel_launch(void* const* d_in, const int* in_sizes, int n_in,
                              void* d_out, int out_size)
{
    const float* M  = (const float*)d_in[0];
    const float* mu = (const float*)d_in[1];
    float* out = (float*)d_out;

    const int grid = N_IMG * (H_DIM / STRIP);  // 2048 blocks
    div_grad_kernel<<<grid, 256>>>(M, mu, out);
}

// round 6
// speedup vs baseline: 1.1175x; 1.1175x over previous
#include <cuda_runtime.h>
#include <cstdint>

// Divergence of (average(M) * gradient(mu)) with periodic boundaries.
// Shapes: (B=16, C=1, H=1024, W=1024) fp32.
// out[p] = sum_ax [ v_ax(p) - v_ax(p - e_ax) ],  v_ax(p) = 0.5*(M[p+e]+M[p])*(mu[p+e]-mu[p])
//
// Block = 256 threads = one full 1024-float row width. Each block processes a
// 4-row strip: 6 rows of M and mu (strip + vertical halo) are staged into
// shared memory with cp.async (12 x 16B per thread, register-free burst MLP),
// then the 4 output rows are computed from smem. Horizontal halos are
// wrap-indexed smem reads; no shuffles, no scalar global loads.

#define H_DIM 1024
#define W_DIM 1024
#define N_IMG 16
#define RSTRIP 4
#define NROWS (RSTRIP + 2)

__device__ __forceinline__ void cp16(uint32_t smem_addr, const void* gptr)
{
    asm volatile("cp.async.cg.shared.global [%0], [%1], 16;\n"
                 :: "r"(smem_addr), "l"(gptr));
}

__global__ __launch_bounds__(256) void div_grad_kernel(
    const float* __restrict__ M,
    const float* __restrict__ mu,
    float* __restrict__ out)
{
    __shared__ float sM[NROWS][W_DIM];
    __shared__ float sU[NROWS][W_DIM];

    const int t     = threadIdx.x;         // 0..255 : float4 column
    const int strip = blockIdx.x & 255;    // 256 strips of 4 rows per image
    const int img   = blockIdx.x >> 8;

    const int h0 = strip << 2;             // 0..1020
    const size_t base = (size_t)img << 20;
    const float* Mi = M  + base;
    const float* Ui = mu + base;
    const int wb = t << 2;

    // Row indices: 0 = h0-1 (wrap), 1..4 = h0..h0+3, 5 = h0+4 (wrap)
    int hrow[NROWS];
    hrow[0] = (h0 - 1) & (H_DIM - 1);
    #pragma unroll
    for (int i = 1; i < NROWS - 1; ++i) hrow[i] = h0 + i - 1;
    hrow[NROWS - 1] = (h0 + RSTRIP) & (H_DIM - 1);

    // Stage 6 rows x 2 arrays via cp.async: 12 independent 16B copies/thread.
    const uint32_t sMb = (uint32_t)__cvta_generic_to_shared(&sM[0][0]);
    const uint32_t sUb = (uint32_t)__cvta_generic_to_shared(&sU[0][0]);
    #pragma unroll
    for (int i = 0; i < NROWS; ++i) {
        const size_t go = ((size_t)hrow[i] << 10) + wb;
        cp16(sMb + (uint32_t)(i * W_DIM + wb) * 4u, Mi + go);
        cp16(sUb + (uint32_t)(i * W_DIM + wb) * 4u, Ui + go);
    }
    asm volatile("cp.async.commit_group;\n" ::: "memory");
    asm volatile("cp.async.wait_group 0;\n" ::: "memory");
    __syncthreads();

    const int wl = (wb - 1) & (W_DIM - 1);
    const int wr = (wb + 4) & (W_DIM - 1);
    float* Oi = out + base;

    #pragma unroll
    for (int r = 0; r < RSTRIP; ++r) {
        const int c = r + 1;
        const float4 m   = *reinterpret_cast<const float4*>(&sM[c][wb]);
        const float4 u   = *reinterpret_cast<const float4*>(&sU[c][wb]);
        const float4 mup = *reinterpret_cast<const float4*>(&sM[c - 1][wb]);
        const float4 uup = *reinterpret_cast<const float4*>(&sU[c - 1][wb]);
        const float4 mdn = *reinterpret_cast<const float4*>(&sM[c + 1][wb]);
        const float4 udn = *reinterpret_cast<const float4*>(&sU[c + 1][wb]);
        const float mL = sM[c][wl], uL = sU[c][wl];
        const float mR = sM[c][wr], uR = sU[c][wr];

        // W-direction forward fluxes (backward flux of elem e == forward of e-1)
        float vm = 0.5f * (m.x + mL)  * (u.x - uL);
        float v0 = 0.5f * (m.y + m.x) * (u.y - u.x);
        float v1 = 0.5f * (m.z + m.y) * (u.z - u.y);
        float v2 = 0.5f * (m.w + m.z) * (u.w - u.z);
        float v3 = 0.5f * (mR  + m.w) * (uR  - u.w);

        float4 res;
        res.x = (v0 - vm) + 0.5f * (mdn.x + m.x) * (udn.x - u.x) - 0.5f * (m.x + mup.x) * (u.x - uup.x);
        res.y = (v1 - v0) + 0.5f * (mdn.y + m.y) * (udn.y - u.y) - 0.5f * (m.y + mup.y) * (u.y - uup.y);
        res.z = (v2 - v1) + 0.5f * (mdn.z + m.z) * (udn.z - u.z) - 0.5f * (m.z + mup.z) * (u.z - uup.z);
        res.w = (v3 - v2) + 0.5f * (mdn.w + m.w) * (udn.w - u.w) - 0.5f * (m.w + mup.w) * (u.w - uup.w);

        __stcs(reinterpret_cast<float4*>(Oi + ((size_t)(h0 + r) << 10) + wb), res);
    }
}

extern "C" void kernel_launch(void* const* d_in, const int* in_sizes, int n_in,
                              void* d_out, int out_size)
{
    const float* M  = (const float*)d_in[0];
    const float* mu = (const float*)d_in[1];
    float* out = (float*)d_out;

    const int grid = N_IMG * (H_DIM / RSTRIP);  // 4096 blocks
    div_grad_kernel<<<grid, 256>>>(M, mu, out);
}